// round 4
// baseline (speedup 1.0000x reference)
#include <cuda_runtime.h>
#include <math.h>

#define D_DIM 256
#define H_DIM 128
#define R_DIM 4

#define MAX_N 50048
#define MAX_E 640000

// Scratch (allocation-free: __device__ globals), 16B-aligned for float4 access
__device__ __align__(16) float g_h[(size_t)R_DIM * MAX_N * H_DIM];   // ~102 MB
__device__ __align__(16) float g_s1[R_DIM * MAX_N];
__device__ __align__(16) float g_s2[R_DIM * MAX_N];
__device__ __align__(16) float g_segsum[R_DIM * MAX_N];
__device__ __align__(16) float g_ew[MAX_E];

// ---------------------------------------------------------------------------
// Init: segsum = 0, out = 0
// ---------------------------------------------------------------------------
__global__ void init_kernel(float* __restrict__ out, int N, int out_elems) {
    int i = blockIdx.x * blockDim.x + threadIdx.x;
    if (i < R_DIM * N) g_segsum[i] = 0.0f;
    for (int j = i; j < out_elems; j += gridDim.x * blockDim.x) out[j] = 0.0f;
}

// ---------------------------------------------------------------------------
// SGEMM: h[r] = x @ W[r] + b[r]
// Block = 128 rows x 128 cols (one relation per blockIdx.y), 256 threads,
// 8x8 register tile per thread, BK=16.
// ---------------------------------------------------------------------------
__global__ __launch_bounds__(256, 2)
void gemm_kernel(const float* __restrict__ x, const float* __restrict__ W,
                 const float* __restrict__ b, int N) {
    const int r  = blockIdx.y;
    const int m0 = blockIdx.x * 128;
    __shared__ __align__(16) float As[16][128];
    __shared__ __align__(16) float Bs[16][128];

    const int tid = threadIdx.x;
    const int tx  = tid & 15;   // 0..15 -> col group
    const int ty  = tid >> 4;   // 0..15 -> row group

    float acc[8][8];
    #pragma unroll
    for (int i = 0; i < 8; i++)
        #pragma unroll
        for (int j = 0; j < 8; j++) acc[i][j] = 0.0f;

    const float* Wr = W + (size_t)r * D_DIM * H_DIM;

    for (int k0 = 0; k0 < D_DIM; k0 += 16) {
        // Load A tile (128 rows x 16 k), stored transposed As[k][m]
        #pragma unroll
        for (int i = 0; i < 2; i++) {
            int idx  = tid * 2 + i;          // float4 index, 512 total
            int arow = idx >> 2;             // 4 float4 per row
            int ak   = (idx & 3) * 4;
            float4 v = make_float4(0.f, 0.f, 0.f, 0.f);
            int gr = m0 + arow;
            if (gr < N) v = *(const float4*)(x + (size_t)gr * D_DIM + k0 + ak);
            As[ak + 0][arow] = v.x;
            As[ak + 1][arow] = v.y;
            As[ak + 2][arow] = v.z;
            As[ak + 3][arow] = v.w;
        }
        // Load B tile (16 k x 128 cols)
        #pragma unroll
        for (int i = 0; i < 2; i++) {
            int idx  = tid * 2 + i;
            int brow = idx >> 5;             // 32 float4 per row
            int bj   = (idx & 31) * 4;
            float4 v = *(const float4*)(Wr + (size_t)(k0 + brow) * H_DIM + bj);
            *(float4*)&Bs[brow][bj] = v;
        }
        __syncthreads();

        #pragma unroll
        for (int k = 0; k < 16; k++) {
            float av[8], bv[8];
            #pragma unroll
            for (int i = 0; i < 8; i++) av[i] = As[k][ty * 8 + i];
            #pragma unroll
            for (int j = 0; j < 8; j++) bv[j] = Bs[k][tx * 8 + j];
            #pragma unroll
            for (int i = 0; i < 8; i++)
                #pragma unroll
                for (int j = 0; j < 8; j++)
                    acc[i][j] = fmaf(av[i], bv[j], acc[i][j]);
        }
        __syncthreads();
    }

    // Epilogue: bias + store to g_h
    const float* br = b + r * H_DIM;
    float bias[8];
    #pragma unroll
    for (int j = 0; j < 8; j++) bias[j] = br[tx * 8 + j];

    #pragma unroll
    for (int i = 0; i < 8; i++) {
        int gr = m0 + ty * 8 + i;
        if (gr < N) {
            float* dst = g_h + ((size_t)r * N + gr) * H_DIM + tx * 8;
            float4 v0 = make_float4(acc[i][0] + bias[0], acc[i][1] + bias[1],
                                    acc[i][2] + bias[2], acc[i][3] + bias[3]);
            float4 v1 = make_float4(acc[i][4] + bias[4], acc[i][5] + bias[5],
                                    acc[i][6] + bias[6], acc[i][7] + bias[7]);
            *(float4*)(dst)     = v0;
            *(float4*)(dst + 4) = v1;
        }
    }
}

// ---------------------------------------------------------------------------
// Per-(r,n) attention scalars: s1 = h . a1, s2 = h . a2   (warp per row)
// ---------------------------------------------------------------------------
__global__ void sdot_kernel(const float* __restrict__ a_att, int N) {
    int widx = blockIdx.x * (blockDim.x >> 5) + (threadIdx.x >> 5);
    int lane = threadIdx.x & 31;
    int total = R_DIM * N;
    if (widx >= total) return;
    const float4 hv = *(const float4*)(g_h + (size_t)widx * H_DIM + lane * 4);
    const float4 a1 = *(const float4*)(a_att + lane * 4);
    const float4 a2 = *(const float4*)(a_att + H_DIM + lane * 4);
    float d1 = hv.x * a1.x + hv.y * a1.y + hv.z * a1.z + hv.w * a1.w;
    float d2 = hv.x * a2.x + hv.y * a2.y + hv.z * a2.z + hv.w * a2.w;
    #pragma unroll
    for (int o = 16; o > 0; o >>= 1) {
        d1 += __shfl_xor_sync(0xFFFFFFFFu, d1, o);
        d2 += __shfl_xor_sync(0xFFFFFFFFu, d2, o);
    }
    if (lane == 0) {
        g_s1[widx] = d1;
        g_s2[widx] = d2;
    }
}

// ---------------------------------------------------------------------------
// Edge pass 1: w = exp(leakyrelu(s1[t,row] + s2[t,col])); segsum += w.
// (No max-subtraction needed: |e| <~ 8 for this data, exp() is safe in fp32,
//  and softmax is shift-invariant so the result matches the reference.)
// NOTE: edge_index / edge_type are int32 (JAX default x64-disabled downcasts
// the requested int64).
// ---------------------------------------------------------------------------
__global__ void edge_w_kernel(const int* __restrict__ ei,
                              const int* __restrict__ et, int N, int E) {
    int e = blockIdx.x * blockDim.x + threadIdx.x;
    if (e >= E) return;
    int row = ei[e];
    int col = ei[E + e];
    int t   = et[e];
    float s  = g_s1[t * N + row] + g_s2[t * N + col];
    float ev = (s >= 0.0f) ? s : 0.2f * s;
    float w  = expf(ev);
    g_ew[e] = w;
    atomicAdd(&g_segsum[t * N + row], w);
}

// ---------------------------------------------------------------------------
// Edge pass 2: out[row] += (w/segsum) * h[t, col]   (warp per edge)
// Each lane handles 4 consecutive floats; scalar float atomicAdd per element.
// ---------------------------------------------------------------------------
__global__ void edge_scatter_kernel(const int* __restrict__ ei,
                                    const int* __restrict__ et,
                                    float* __restrict__ out, int N, int E) {
    int e    = blockIdx.x * (blockDim.x >> 5) + (threadIdx.x >> 5);
    int lane = threadIdx.x & 31;
    if (e >= E) return;
    int row = ei[e];
    int col = ei[E + e];
    int t   = et[e];
    float w    = g_ew[e];
    float ssum = g_segsum[t * N + row];
    float alpha = w / (ssum > 0.0f ? ssum : 1.0f);

    const float4 hv = *(const float4*)(g_h + ((size_t)t * N + col) * H_DIM + lane * 4);
    float* dst = out + (size_t)row * H_DIM + lane * 4;
    atomicAdd(dst + 0, hv.x * alpha);
    atomicAdd(dst + 1, hv.y * alpha);
    atomicAdd(dst + 2, hv.z * alpha);
    atomicAdd(dst + 3, hv.w * alpha);
}

// ---------------------------------------------------------------------------
extern "C" void kernel_launch(void* const* d_in, const int* in_sizes, int n_in,
                              void* d_out, int out_size) {
    const float* x  = (const float*)d_in[0];
    const int*   ei = (const int*)d_in[1];
    const int*   et = (const int*)d_in[2];
    const float* a  = (const float*)d_in[3];
    const float* W  = (const float*)d_in[4];
    const float* b  = (const float*)d_in[5];
    float* out = (float*)d_out;

    int N = in_sizes[0] / D_DIM;   // 50000
    int E = in_sizes[2];           // 640000

    // Zero segsum + out
    {
        int work = (R_DIM * N > out_size) ? R_DIM * N : out_size;
        int blocks = (work + 255) / 256;
        if (blocks > 4096) blocks = 4096;
        init_kernel<<<blocks, 256>>>(out, N, out_size);
    }

    dim3 ggrid((N + 127) / 128, R_DIM);
    gemm_kernel<<<ggrid, 256>>>(x, W, b, N);

    int total_rows = R_DIM * N;
    sdot_kernel<<<(total_rows + 7) / 8, 256>>>(a, N);

    edge_w_kernel<<<(E + 255) / 256, 256>>>(ei, et, N, E);
    edge_scatter_kernel<<<(E + 7) / 8, 256>>>(ei, et, out, N, E);
}

// round 6
// speedup vs baseline: 1.4028x; 1.4028x over previous
#include <cuda_runtime.h>
#include <cuda_bf16.h>
#include <math.h>
#include <stdint.h>

#define D_DIM 256
#define H_DIM 128
#define R_DIM 4

#define MAX_N 50048
#define MAX_E 640000

// ---------------------------------------------------------------------------
// Scratch (allocation-free: __device__ globals)
// ---------------------------------------------------------------------------
__device__ __align__(16) float g_h[(size_t)R_DIM * MAX_N * H_DIM];   // ~102 MB
__device__ __align__(16) float g_s1[R_DIM * MAX_N];
__device__ __align__(16) float g_s2[R_DIM * MAX_N];
__device__ __align__(16) float g_segsum[R_DIM * MAX_N];
__device__ __align__(16) float g_ew[MAX_E];
__device__ __align__(16) __nv_bfloat16 g_xhi[(size_t)MAX_N * D_DIM];
__device__ __align__(16) __nv_bfloat16 g_xlo[(size_t)MAX_N * D_DIM];
__device__ __align__(16) __nv_bfloat16 g_wthi[R_DIM * H_DIM * D_DIM];  // [r][h][d]
__device__ __align__(16) __nv_bfloat16 g_wtlo[R_DIM * H_DIM * D_DIM];

__device__ __forceinline__ uint32_t smem_u32(const void* p) {
    uint32_t a;
    asm("{ .reg .u64 t; cvta.to.shared.u64 t, %1; cvt.u32.u64 %0, t; }"
        : "=r"(a) : "l"(p));
    return a;
}

__device__ __forceinline__ void ldm_x4(uint32_t& r0, uint32_t& r1,
                                       uint32_t& r2, uint32_t& r3, uint32_t addr) {
    asm volatile("ldmatrix.sync.aligned.m8n8.x4.shared.b16 {%0,%1,%2,%3}, [%4];"
                 : "=r"(r0), "=r"(r1), "=r"(r2), "=r"(r3) : "r"(addr));
}

__device__ __forceinline__ void mma_bf16(float* c, uint32_t a0, uint32_t a1,
                                         uint32_t a2, uint32_t a3,
                                         uint32_t b0, uint32_t b1) {
    asm volatile("mma.sync.aligned.m16n8k16.row.col.f32.bf16.bf16.f32 "
                 "{%0,%1,%2,%3}, {%4,%5,%6,%7}, {%8,%9}, {%0,%1,%2,%3};"
                 : "+f"(c[0]), "+f"(c[1]), "+f"(c[2]), "+f"(c[3])
                 : "r"(a0), "r"(a1), "r"(a2), "r"(a3), "r"(b0), "r"(b1));
}

// ---------------------------------------------------------------------------
// Init: segsum = 0, out = 0
// ---------------------------------------------------------------------------
__global__ void init_kernel(float* __restrict__ out, int N, int out_elems) {
    int i = blockIdx.x * blockDim.x + threadIdx.x;
    if (i < R_DIM * N) g_segsum[i] = 0.0f;
    for (int j = i; j < out_elems; j += gridDim.x * blockDim.x) out[j] = 0.0f;
}

// ---------------------------------------------------------------------------
// Split x into bf16 hi/lo (hi = bf16(x), lo = bf16(x - hi))
// ---------------------------------------------------------------------------
__global__ void conv_x_kernel(const float* __restrict__ x, int total4) {
    int i = blockIdx.x * blockDim.x + threadIdx.x;
    if (i >= total4) return;
    float4 v = ((const float4*)x)[i];
    __nv_bfloat16 h0 = __float2bfloat16(v.x), h1 = __float2bfloat16(v.y);
    __nv_bfloat16 h2 = __float2bfloat16(v.z), h3 = __float2bfloat16(v.w);
    __nv_bfloat16 l0 = __float2bfloat16(v.x - __bfloat162float(h0));
    __nv_bfloat16 l1 = __float2bfloat16(v.y - __bfloat162float(h1));
    __nv_bfloat16 l2 = __float2bfloat16(v.z - __bfloat162float(h2));
    __nv_bfloat16 l3 = __float2bfloat16(v.w - __bfloat162float(h3));
    __nv_bfloat162* ph = (__nv_bfloat162*)g_xhi;
    __nv_bfloat162* pl = (__nv_bfloat162*)g_xlo;
    ph[2 * i]     = __nv_bfloat162(h0, h1);
    ph[2 * i + 1] = __nv_bfloat162(h2, h3);
    pl[2 * i]     = __nv_bfloat162(l0, l1);
    pl[2 * i + 1] = __nv_bfloat162(l2, l3);
}

// ---------------------------------------------------------------------------
// Transpose + split W:  Wt[r][h][d] = W[r][d][h]
// ---------------------------------------------------------------------------
__global__ void conv_w_kernel(const float* __restrict__ W) {
    int i = blockIdx.x * blockDim.x + threadIdx.x;
    if (i >= R_DIM * D_DIM * H_DIM) return;
    int r = i >> 15;
    int rem = i & 32767;
    int d = rem >> 7;
    int h = rem & 127;
    float v = W[i];
    __nv_bfloat16 hi = __float2bfloat16(v);
    __nv_bfloat16 lo = __float2bfloat16(v - __bfloat162float(hi));
    int dst = ((r * H_DIM + h) << 8) + d;
    g_wthi[dst] = hi;
    g_wtlo[dst] = lo;
}

// ---------------------------------------------------------------------------
// HMMA GEMM: h[r] = x @ W[r] + b[r] via split-bf16 (hi*hi + hi*lo + lo*hi).
// CTA: 128(M) x 128(N), 256 threads = 8 warps, warp tile 32x64.
// K = 256 in 4 chunks of 64. mma.m16n8k16 row.col, non-trans ldmatrix
// (A: [M,K] K-major, B: [N,K] K-major). SW128-swizzled smem tiles.
// Epilogue: bias + fused s1/s2 dots + g_h store.
// ---------------------------------------------------------------------------
#define SM_A_HI 0
#define SM_A_LO 16384
#define SM_B_HI 32768
#define SM_B_LO 49152
#define H_STRIDE 132
#define GEMM_DYN_SMEM (128 * H_STRIDE * 4 + 1024)   // 67584 + 1024 (>= 64KB tiles)

__global__ __launch_bounds__(256, 1)
void gemm_mma_kernel(const float* __restrict__ bias_g,
                     const float* __restrict__ a_att, int N) {
    extern __shared__ char dynsm[];
    __shared__ float s_a[2 * H_DIM];
    __shared__ float s_bias[H_DIM];

    const uint32_t raw  = smem_u32(dynsm);
    const uint32_t base = (raw + 1023u) & ~1023u;
    const uint32_t pad  = base - raw;

    const int tid    = threadIdx.x;
    const int wid    = tid >> 5;
    const int lane   = tid & 31;
    const int warp_m = wid & 3;       // 4 warps over M (32 rows each)
    const int warp_n = wid >> 2;      // 2 warps over N (64 cols each)
    const int r      = blockIdx.y;
    const int m0     = blockIdx.x * 128;

    for (int i = tid; i < 2 * H_DIM; i += 256) s_a[i] = a_att[i];
    if (tid < H_DIM) s_bias[tid] = bias_g[r * H_DIM + tid];

    // Per-lane ldmatrix row precomputation (row*128, xor nibble)
    const int l16   = lane & 15;
    const int lhalf = (lane >> 4) << 4;   // 0 or 16 bytes
    uint32_t prodA[2], xrA[2];
    #pragma unroll
    for (int mb = 0; mb < 2; mb++) {
        int rA = warp_m * 32 + mb * 16 + l16;
        prodA[mb] = (uint32_t)(rA * 128);
        xrA[mb]   = (uint32_t)((rA & 7) << 4);
    }
    uint32_t prodB[4], xrB[4];
    #pragma unroll
    for (int nb = 0; nb < 4; nb++) {
        int rB = warp_n * 64 + nb * 16 + l16;
        prodB[nb] = (uint32_t)(rB * 128);
        xrB[nb]   = (uint32_t)((rB & 7) << 4);
    }

    float acc[64];   // [mblk(2)][n8(8)][4]
    #pragma unroll
    for (int i = 0; i < 64; i++) acc[i] = 0.0f;

    const char* xhi = (const char*)g_xhi;
    const char* xlo = (const char*)g_xlo;
    const char* whi = (const char*)g_wthi;
    const char* wlo = (const char*)g_wtlo;

    for (int c = 0; c < 4; c++) {
        const int k0 = c * 64;
        __syncthreads();
        // Load 4 tiles: 128 rows x 128B each, SW128-swizzled, uint4 chunks.
        #pragma unroll
        for (int it = 0; it < 4; it++) {
            int i   = tid + it * 256;      // 0..1023
            int row = i >> 3;
            int u   = (i & 7) * 16;
            uint32_t sw = (uint32_t)(row * 128 + (u ^ ((row & 7) << 4)));
            int gr = m0 + row;
            uint4 vh = make_uint4(0, 0, 0, 0), vl = make_uint4(0, 0, 0, 0);
            if (gr < N) {
                size_t off = ((size_t)gr * D_DIM + k0) * 2 + u;
                vh = *(const uint4*)(xhi + off);
                vl = *(const uint4*)(xlo + off);
            }
            *(uint4*)(dynsm + pad + SM_A_HI + sw) = vh;
            *(uint4*)(dynsm + pad + SM_A_LO + sw) = vl;
            size_t woff = ((size_t)(r * H_DIM + row) * D_DIM + k0) * 2 + u;
            *(uint4*)(dynsm + pad + SM_B_HI + sw) = *(const uint4*)(whi + woff);
            *(uint4*)(dynsm + pad + SM_B_LO + sw) = *(const uint4*)(wlo + woff);
        }
        __syncthreads();

        // 3 terms: (A_hi,B_hi), (A_hi,B_lo), (A_lo,B_hi)
        #pragma unroll
        for (int term = 0; term < 3; term++) {
            const uint32_t abase = base + ((term == 2) ? SM_A_LO : SM_A_HI);
            const uint32_t bbase = base + ((term == 1) ? SM_B_LO : SM_B_HI);
            #pragma unroll
            for (int ks = 0; ks < 4; ks++) {
                const uint32_t cb = (uint32_t)(ks * 32 + lhalf);
                uint32_t a[2][4];
                #pragma unroll
                for (int mb = 0; mb < 2; mb++)
                    ldm_x4(a[mb][0], a[mb][1], a[mb][2], a[mb][3],
                           abase + prodA[mb] + (cb ^ xrA[mb]));
                uint32_t b[4][4];
                #pragma unroll
                for (int nb = 0; nb < 4; nb++)
                    ldm_x4(b[nb][0], b[nb][1], b[nb][2], b[nb][3],
                           bbase + prodB[nb] + (cb ^ xrB[nb]));
                #pragma unroll
                for (int mb = 0; mb < 2; mb++) {
                    #pragma unroll
                    for (int nb = 0; nb < 4; nb++) {
                        // x4 result: r0 = n[0:8) k-lo, r1 = n[8:16) k-lo,
                        //            r2 = n[0:8) k-hi, r3 = n[8:16) k-hi
                        mma_bf16(&acc[(mb * 8 + nb * 2) * 4],
                                 a[mb][0], a[mb][1], a[mb][2], a[mb][3],
                                 b[nb][0], b[nb][2]);
                        mma_bf16(&acc[(mb * 8 + nb * 2 + 1) * 4],
                                 a[mb][0], a[mb][1], a[mb][2], a[mb][3],
                                 b[nb][1], b[nb][3]);
                    }
                }
            }
        }
    }

    // Epilogue: acc -> smem h tile
    __syncthreads();
    float* hs = (float*)(dynsm + pad);
    const int gq = lane >> 2;
    const int q4 = lane & 3;
    #pragma unroll
    for (int mb = 0; mb < 2; mb++) {
        #pragma unroll
        for (int n8 = 0; n8 < 8; n8++) {
            const float* cc = &acc[(mb * 8 + n8) * 4];
            int rr  = warp_m * 32 + mb * 16 + gq;
            int col = warp_n * 64 + n8 * 8 + q4 * 2;
            hs[rr * H_STRIDE + col]           = cc[0];
            hs[rr * H_STRIDE + col + 1]       = cc[1];
            hs[(rr + 8) * H_STRIDE + col]     = cc[2];
            hs[(rr + 8) * H_STRIDE + col + 1] = cc[3];
        }
    }
    __syncthreads();

    // Per-row: bias + s1/s2 dots + store h (each warp: 16 rows)
    #pragma unroll
    for (int rr = 0; rr < 16; rr++) {
        int lrow = wid * 16 + rr;
        int grow = m0 + lrow;
        if (grow >= N) continue;
        float4 hv = *(const float4*)&hs[lrow * H_STRIDE + lane * 4];
        int cb = lane * 4;
        hv.x += s_bias[cb];     hv.y += s_bias[cb + 1];
        hv.z += s_bias[cb + 2]; hv.w += s_bias[cb + 3];
        float d1 = hv.x * s_a[cb]         + hv.y * s_a[cb + 1]
                 + hv.z * s_a[cb + 2]     + hv.w * s_a[cb + 3];
        float d2 = hv.x * s_a[H_DIM + cb]     + hv.y * s_a[H_DIM + cb + 1]
                 + hv.z * s_a[H_DIM + cb + 2] + hv.w * s_a[H_DIM + cb + 3];
        #pragma unroll
        for (int o = 16; o > 0; o >>= 1) {
            d1 += __shfl_xor_sync(0xFFFFFFFFu, d1, o);
            d2 += __shfl_xor_sync(0xFFFFFFFFu, d2, o);
        }
        *(float4*)(g_h + ((size_t)r * N + grow) * H_DIM + lane * 4) = hv;
        if (lane == 0) {
            g_s1[r * N + grow] = d1;
            g_s2[r * N + grow] = d2;
        }
    }
}

// ---------------------------------------------------------------------------
// Edge pass 1: w = exp(leakyrelu(s1[t,row] + s2[t,col])); segsum += w.
// (Softmax is shift-invariant; |e| stays small enough for direct exp.)
// edge_index / edge_type are int32.
// ---------------------------------------------------------------------------
__global__ void edge_w_kernel(const int* __restrict__ ei,
                              const int* __restrict__ et, int N, int E) {
    int e = blockIdx.x * blockDim.x + threadIdx.x;
    if (e >= E) return;
    int row = ei[e];
    int col = ei[E + e];
    int t   = et[e];
    float s  = g_s1[t * N + row] + g_s2[t * N + col];
    float ev = (s >= 0.0f) ? s : 0.2f * s;
    float w  = expf(ev);
    g_ew[e] = w;
    atomicAdd(&g_segsum[t * N + row], w);
}

// ---------------------------------------------------------------------------
// Edge pass 2: out[row] += (w/segsum) * h[t, col]   (warp per edge)
// ---------------------------------------------------------------------------
__global__ void edge_scatter_kernel(const int* __restrict__ ei,
                                    const int* __restrict__ et,
                                    float* __restrict__ out, int N, int E) {
    int e    = blockIdx.x * (blockDim.x >> 5) + (threadIdx.x >> 5);
    int lane = threadIdx.x & 31;
    if (e >= E) return;
    int row = ei[e];
    int col = ei[E + e];
    int t   = et[e];
    float w    = g_ew[e];
    float ssum = g_segsum[t * N + row];
    float alpha = w / (ssum > 0.0f ? ssum : 1.0f);

    const float4 hv = *(const float4*)(g_h + ((size_t)t * N + col) * H_DIM + lane * 4);
    float* dst = out + (size_t)row * H_DIM + lane * 4;
    atomicAdd(dst + 0, hv.x * alpha);
    atomicAdd(dst + 1, hv.y * alpha);
    atomicAdd(dst + 2, hv.z * alpha);
    atomicAdd(dst + 3, hv.w * alpha);
}

// ---------------------------------------------------------------------------
extern "C" void kernel_launch(void* const* d_in, const int* in_sizes, int n_in,
                              void* d_out, int out_size) {
    const float* x  = (const float*)d_in[0];
    const int*   ei = (const int*)d_in[1];
    const int*   et = (const int*)d_in[2];
    const float* a  = (const float*)d_in[3];
    const float* W  = (const float*)d_in[4];
    const float* b  = (const float*)d_in[5];
    float* out = (float*)d_out;

    int N = in_sizes[0] / D_DIM;   // 50000
    int E = in_sizes[2];           // 640000

    // Zero segsum + out
    {
        int work = (R_DIM * N > out_size) ? R_DIM * N : out_size;
        int blocks = (work + 255) / 256;
        if (blocks > 4096) blocks = 4096;
        init_kernel<<<blocks, 256>>>(out, N, out_size);
    }

    // Split inputs to bf16 hi/lo
    int total4 = N * (D_DIM / 4);
    conv_x_kernel<<<(total4 + 255) / 256, 256>>>(x, total4);
    conv_w_kernel<<<(R_DIM * D_DIM * H_DIM + 255) / 256, 256>>>(W);

    // Tensor-core GEMM (+fused s1/s2)
    cudaFuncSetAttribute(gemm_mma_kernel,
                         cudaFuncAttributeMaxDynamicSharedMemorySize, GEMM_DYN_SMEM);
    dim3 ggrid((N + 127) / 128, R_DIM);
    gemm_mma_kernel<<<ggrid, 256, GEMM_DYN_SMEM>>>(b, a, N);

    edge_w_kernel<<<(E + 255) / 256, 256>>>(ei, et, N, E);
    edge_scatter_kernel<<<(E + 7) / 8, 256>>>(ei, et, out, N, E);
}

// round 7
// speedup vs baseline: 1.8428x; 1.3136x over previous
#include <cuda_runtime.h>
#include <cuda_bf16.h>
#include <math.h>
#include <stdint.h>

#define D_DIM 256
#define H_DIM 128
#define R_DIM 4

#define MAX_N 50048
#define MAX_E 640000

// ---------------------------------------------------------------------------
// Scratch (allocation-free: __device__ globals)
// ---------------------------------------------------------------------------
__device__ __align__(16) float g_h[(size_t)R_DIM * MAX_N * H_DIM];   // ~102 MB
__device__ __align__(16) float g_s1[R_DIM * MAX_N];
__device__ __align__(16) float g_s2[R_DIM * MAX_N];
__device__ __align__(16) float g_segsum[R_DIM * MAX_N];
__device__ __align__(16) float g_ew[MAX_E];
__device__ __align__(16) __nv_bfloat16 g_xhi[(size_t)MAX_N * D_DIM];  // rows >= N stay 0
__device__ __align__(16) __nv_bfloat16 g_xlo[(size_t)MAX_N * D_DIM];
__device__ __align__(16) __nv_bfloat16 g_wthi[R_DIM * H_DIM * D_DIM];  // [r][h][d]
__device__ __align__(16) __nv_bfloat16 g_wtlo[R_DIM * H_DIM * D_DIM];

__device__ __forceinline__ uint32_t smem_u32(const void* p) {
    uint32_t a;
    asm("{ .reg .u64 t; cvta.to.shared.u64 t, %1; cvt.u32.u64 %0, t; }"
        : "=r"(a) : "l"(p));
    return a;
}

__device__ __forceinline__ void cp16(uint32_t dst, const void* src) {
    asm volatile("cp.async.cg.shared.global [%0], [%1], 16;"
                 :: "r"(dst), "l"(src) : "memory");
}
#define CP_COMMIT() asm volatile("cp.async.commit_group;" ::: "memory")
#define CP_WAIT(n)  asm volatile("cp.async.wait_group %0;" :: "n"(n) : "memory")

__device__ __forceinline__ void ldm_x4(uint32_t& r0, uint32_t& r1,
                                       uint32_t& r2, uint32_t& r3, uint32_t addr) {
    asm volatile("ldmatrix.sync.aligned.m8n8.x4.shared.b16 {%0,%1,%2,%3}, [%4];"
                 : "=r"(r0), "=r"(r1), "=r"(r2), "=r"(r3) : "r"(addr));
}

__device__ __forceinline__ void mma_bf16(float* c, uint32_t a0, uint32_t a1,
                                         uint32_t a2, uint32_t a3,
                                         uint32_t b0, uint32_t b1) {
    asm volatile("mma.sync.aligned.m16n8k16.row.col.f32.bf16.bf16.f32 "
                 "{%0,%1,%2,%3}, {%4,%5,%6,%7}, {%8,%9}, {%0,%1,%2,%3};"
                 : "+f"(c[0]), "+f"(c[1]), "+f"(c[2]), "+f"(c[3])
                 : "r"(a0), "r"(a1), "r"(a2), "r"(a3), "r"(b0), "r"(b1));
}

// ---------------------------------------------------------------------------
// Init: segsum = 0, out = 0
// ---------------------------------------------------------------------------
__global__ void init_kernel(float* __restrict__ out, int N, int out_elems) {
    int i = blockIdx.x * blockDim.x + threadIdx.x;
    if (i < R_DIM * N) g_segsum[i] = 0.0f;
    for (int j = i; j < out_elems; j += gridDim.x * blockDim.x) out[j] = 0.0f;
}

// ---------------------------------------------------------------------------
// Split x into bf16 hi/lo (hi = bf16(x), lo = bf16(x - hi))
// ---------------------------------------------------------------------------
__global__ void conv_x_kernel(const float* __restrict__ x, int total4) {
    int i = blockIdx.x * blockDim.x + threadIdx.x;
    if (i >= total4) return;
    float4 v = ((const float4*)x)[i];
    __nv_bfloat16 h0 = __float2bfloat16(v.x), h1 = __float2bfloat16(v.y);
    __nv_bfloat16 h2 = __float2bfloat16(v.z), h3 = __float2bfloat16(v.w);
    __nv_bfloat16 l0 = __float2bfloat16(v.x - __bfloat162float(h0));
    __nv_bfloat16 l1 = __float2bfloat16(v.y - __bfloat162float(h1));
    __nv_bfloat16 l2 = __float2bfloat16(v.z - __bfloat162float(h2));
    __nv_bfloat16 l3 = __float2bfloat16(v.w - __bfloat162float(h3));
    __nv_bfloat162* ph = (__nv_bfloat162*)g_xhi;
    __nv_bfloat162* pl = (__nv_bfloat162*)g_xlo;
    ph[2 * i]     = __nv_bfloat162(h0, h1);
    ph[2 * i + 1] = __nv_bfloat162(h2, h3);
    pl[2 * i]     = __nv_bfloat162(l0, l1);
    pl[2 * i + 1] = __nv_bfloat162(l2, l3);
}

// ---------------------------------------------------------------------------
// Transpose + split W:  Wt[r][h][d] = W[r][d][h]
// ---------------------------------------------------------------------------
__global__ void conv_w_kernel(const float* __restrict__ W) {
    int i = blockIdx.x * blockDim.x + threadIdx.x;
    if (i >= R_DIM * D_DIM * H_DIM) return;
    int r = i >> 15;
    int rem = i & 32767;
    int d = rem >> 7;
    int h = rem & 127;
    float v = W[i];
    __nv_bfloat16 hi = __float2bfloat16(v);
    __nv_bfloat16 lo = __float2bfloat16(v - __bfloat162float(hi));
    int dst = ((r * H_DIM + h) << 8) + d;
    g_wthi[dst] = hi;
    g_wtlo[dst] = lo;
}

// ---------------------------------------------------------------------------
// HMMA GEMM with 2-stage cp.async pipeline.
// h[r] = x @ W[r] + b[r] via split-bf16 (hi*hi + hi*lo + lo*hi).
// CTA: 128(M) x 128(N), 256 threads = 8 warps, warp tile 32x64.
// K = 256 in 4 chunks of 64; chunk c+2 streams in while c computes.
// Epilogue: bias + fused s1/s2 dots + g_h store.
// ---------------------------------------------------------------------------
#define SM_A_HI 0
#define SM_A_LO 16384
#define SM_B_HI 32768
#define SM_B_LO 49152
#define STAGE_BYTES 65536
#define GEMM_DYN_SMEM (2 * STAGE_BYTES + 1024)   // 132 KB

__global__ __launch_bounds__(256, 1)
void gemm_mma_kernel(const float* __restrict__ bias_g,
                     const float* __restrict__ a_att, int N) {
    extern __shared__ char dynsm[];
    __shared__ float s_a[2 * H_DIM];
    __shared__ float s_bias[H_DIM];

    const uint32_t raw  = smem_u32(dynsm);
    const uint32_t base = (raw + 1023u) & ~1023u;
    const uint32_t pad  = base - raw;

    const int tid    = threadIdx.x;
    const int wid    = tid >> 5;
    const int lane   = tid & 31;
    const int warp_m = wid & 3;       // 4 warps over M (32 rows each)
    const int warp_n = wid >> 2;      // 2 warps over N (64 cols each)
    const int r      = blockIdx.y;
    const int m0     = blockIdx.x * 128;

    for (int i = tid; i < 2 * H_DIM; i += 256) s_a[i] = a_att[i];
    if (tid < H_DIM) s_bias[tid] = bias_g[r * H_DIM + tid];

    const char* xhi = (const char*)g_xhi;
    const char* xlo = (const char*)g_xlo;
    const char* whi = (const char*)g_wthi;
    const char* wlo = (const char*)g_wtlo;

    // Per-thread load slots (4 iters x 256 threads = 1024 slots = 128 rows x 8)
    int lrow[4], lu[4];
    uint32_t lsw[4];
    #pragma unroll
    for (int it = 0; it < 4; it++) {
        int i  = tid + it * 256;
        lrow[it] = i >> 3;
        lu[it]   = (i & 7) * 16;
        lsw[it]  = (uint32_t)(lrow[it] * 128 + (lu[it] ^ ((lrow[it] & 7) << 4)));
    }

    // Issue loads for chunk c into buffer buf (rows >= N read zeros from g_x*)
    auto issue_chunk = [&](int c, int buf) {
        const int k0 = c * 64;
        const uint32_t sb = base + buf * STAGE_BYTES;
        #pragma unroll
        for (int it = 0; it < 4; it++) {
            size_t aoff = ((size_t)(m0 + lrow[it]) * D_DIM + k0) * 2 + lu[it];
            cp16(sb + SM_A_HI + lsw[it], xhi + aoff);
            cp16(sb + SM_A_LO + lsw[it], xlo + aoff);
            size_t woff = ((size_t)(r * H_DIM + lrow[it]) * D_DIM + k0) * 2 + lu[it];
            cp16(sb + SM_B_HI + lsw[it], whi + woff);
            cp16(sb + SM_B_LO + lsw[it], wlo + woff);
        }
        CP_COMMIT();
    };

    // Per-lane ldmatrix row precomputation
    const int l16   = lane & 15;
    const int lhalf = (lane >> 4) << 4;
    uint32_t prodA[2], xrA[2];
    #pragma unroll
    for (int mb = 0; mb < 2; mb++) {
        int rA = warp_m * 32 + mb * 16 + l16;
        prodA[mb] = (uint32_t)(rA * 128);
        xrA[mb]   = (uint32_t)((rA & 7) << 4);
    }
    uint32_t prodB[4], xrB[4];
    #pragma unroll
    for (int nb = 0; nb < 4; nb++) {
        int rB = warp_n * 64 + nb * 16 + l16;
        prodB[nb] = (uint32_t)(rB * 128);
        xrB[nb]   = (uint32_t)((rB & 7) << 4);
    }

    float acc[64];
    #pragma unroll
    for (int i = 0; i < 64; i++) acc[i] = 0.0f;

    issue_chunk(0, 0);
    issue_chunk(1, 1);

    #pragma unroll
    for (int c = 0; c < 4; c++) {
        if (c < 3) { CP_WAIT(1); } else { CP_WAIT(0); }
        __syncthreads();

        const uint32_t sb = base + (c & 1) * STAGE_BYTES;
        #pragma unroll
        for (int term = 0; term < 3; term++) {
            const uint32_t abase = sb + ((term == 2) ? SM_A_LO : SM_A_HI);
            const uint32_t bbase = sb + ((term == 1) ? SM_B_LO : SM_B_HI);
            #pragma unroll
            for (int ks = 0; ks < 4; ks++) {
                const uint32_t cb = (uint32_t)(ks * 32 + lhalf);
                uint32_t a[2][4];
                #pragma unroll
                for (int mb = 0; mb < 2; mb++)
                    ldm_x4(a[mb][0], a[mb][1], a[mb][2], a[mb][3],
                           abase + prodA[mb] + (cb ^ xrA[mb]));
                uint32_t b[4][4];
                #pragma unroll
                for (int nb = 0; nb < 4; nb++)
                    ldm_x4(b[nb][0], b[nb][1], b[nb][2], b[nb][3],
                           bbase + prodB[nb] + (cb ^ xrB[nb]));
                #pragma unroll
                for (int mb = 0; mb < 2; mb++) {
                    #pragma unroll
                    for (int nb = 0; nb < 4; nb++) {
                        mma_bf16(&acc[(mb * 8 + nb * 2) * 4],
                                 a[mb][0], a[mb][1], a[mb][2], a[mb][3],
                                 b[nb][0], b[nb][2]);
                        mma_bf16(&acc[(mb * 8 + nb * 2 + 1) * 4],
                                 a[mb][0], a[mb][1], a[mb][2], a[mb][3],
                                 b[nb][1], b[nb][3]);
                    }
                }
            }
        }
        __syncthreads();
        if (c + 2 < 4) issue_chunk(c + 2, c & 1);
    }

    // Epilogue: acc -> smem h tile (reuses pipeline buffers)
    #define H_STRIDE 132
    float* hs = (float*)(dynsm + pad);
    const int gq = lane >> 2;
    const int q4 = lane & 3;
    #pragma unroll
    for (int mb = 0; mb < 2; mb++) {
        #pragma unroll
        for (int n8 = 0; n8 < 8; n8++) {
            const float* cc = &acc[(mb * 8 + n8) * 4];
            int rr  = warp_m * 32 + mb * 16 + gq;
            int col = warp_n * 64 + n8 * 8 + q4 * 2;
            hs[rr * H_STRIDE + col]           = cc[0];
            hs[rr * H_STRIDE + col + 1]       = cc[1];
            hs[(rr + 8) * H_STRIDE + col]     = cc[2];
            hs[(rr + 8) * H_STRIDE + col + 1] = cc[3];
        }
    }
    __syncthreads();

    // Per-row: bias + s1/s2 dots + store h (each warp: 16 rows)
    #pragma unroll
    for (int rr = 0; rr < 16; rr++) {
        int lrow2 = wid * 16 + rr;
        int grow  = m0 + lrow2;
        if (grow >= N) continue;
        float4 hv = *(const float4*)&hs[lrow2 * H_STRIDE + lane * 4];
        int cb = lane * 4;
        hv.x += s_bias[cb];     hv.y += s_bias[cb + 1];
        hv.z += s_bias[cb + 2]; hv.w += s_bias[cb + 3];
        float d1 = hv.x * s_a[cb]         + hv.y * s_a[cb + 1]
                 + hv.z * s_a[cb + 2]     + hv.w * s_a[cb + 3];
        float d2 = hv.x * s_a[H_DIM + cb]     + hv.y * s_a[H_DIM + cb + 1]
                 + hv.z * s_a[H_DIM + cb + 2] + hv.w * s_a[H_DIM + cb + 3];
        #pragma unroll
        for (int o = 16; o > 0; o >>= 1) {
            d1 += __shfl_xor_sync(0xFFFFFFFFu, d1, o);
            d2 += __shfl_xor_sync(0xFFFFFFFFu, d2, o);
        }
        *(float4*)(g_h + ((size_t)r * N + grow) * H_DIM + lane * 4) = hv;
        if (lane == 0) {
            g_s1[r * N + grow] = d1;
            g_s2[r * N + grow] = d2;
        }
    }
}

// ---------------------------------------------------------------------------
// Edge pass 1: w = exp(leakyrelu(s1[t,row] + s2[t,col])); segsum += w.
// (Softmax is shift-invariant; |e| stays small enough for direct exp.)
// edge_index / edge_type are int32.
// ---------------------------------------------------------------------------
__global__ void edge_w_kernel(const int* __restrict__ ei,
                              const int* __restrict__ et, int N, int E) {
    int e = blockIdx.x * blockDim.x + threadIdx.x;
    if (e >= E) return;
    int row = ei[e];
    int col = ei[E + e];
    int t   = et[e];
    float s  = g_s1[t * N + row] + g_s2[t * N + col];
    float ev = (s >= 0.0f) ? s : 0.2f * s;
    float w  = expf(ev);
    g_ew[e] = w;
    atomicAdd(&g_segsum[t * N + row], w);
}

// ---------------------------------------------------------------------------
// Edge pass 2: out[row] += (w/segsum) * h[t, col]   (warp per edge)
// Vector RED: one red.global.add.v4.f32 per lane (4x fewer RED ops).
// ---------------------------------------------------------------------------
__global__ void edge_scatter_kernel(const int* __restrict__ ei,
                                    const int* __restrict__ et,
                                    float* __restrict__ out, int N, int E) {
    int e    = blockIdx.x * (blockDim.x >> 5) + (threadIdx.x >> 5);
    int lane = threadIdx.x & 31;
    if (e >= E) return;
    int row = ei[e];
    int col = ei[E + e];
    int t   = et[e];
    float w    = g_ew[e];
    float ssum = g_segsum[t * N + row];
    float alpha = w / (ssum > 0.0f ? ssum : 1.0f);

    const float4 hv = *(const float4*)(g_h + ((size_t)t * N + col) * H_DIM + lane * 4);
    float* dst = out + (size_t)row * H_DIM + lane * 4;
    asm volatile("red.global.add.v4.f32 [%0], {%1,%2,%3,%4};"
                 :: "l"(dst), "f"(hv.x * alpha), "f"(hv.y * alpha),
                    "f"(hv.z * alpha), "f"(hv.w * alpha)
                 : "memory");
}

// ---------------------------------------------------------------------------
extern "C" void kernel_launch(void* const* d_in, const int* in_sizes, int n_in,
                              void* d_out, int out_size) {
    const float* x  = (const float*)d_in[0];
    const int*   ei = (const int*)d_in[1];
    const int*   et = (const int*)d_in[2];
    const float* a  = (const float*)d_in[3];
    const float* W  = (const float*)d_in[4];
    const float* b  = (const float*)d_in[5];
    float* out = (float*)d_out;

    int N = in_sizes[0] / D_DIM;   // 50000
    int E = in_sizes[2];           // 640000

    // Zero segsum + out
    {
        int work = (R_DIM * N > out_size) ? R_DIM * N : out_size;
        int blocks = (work + 255) / 256;
        if (blocks > 4096) blocks = 4096;
        init_kernel<<<blocks, 256>>>(out, N, out_size);
    }

    // Split inputs to bf16 hi/lo
    int total4 = N * (D_DIM / 4);
    conv_x_kernel<<<(total4 + 255) / 256, 256>>>(x, total4);
    conv_w_kernel<<<(R_DIM * D_DIM * H_DIM + 255) / 256, 256>>>(W);

    // Tensor-core GEMM (+fused s1/s2), 2-stage cp.async pipeline
    cudaFuncSetAttribute(gemm_mma_kernel,
                         cudaFuncAttributeMaxDynamicSharedMemorySize, GEMM_DYN_SMEM);
    dim3 ggrid((N + 127) / 128, R_DIM);
    gemm_mma_kernel<<<ggrid, 256, GEMM_DYN_SMEM>>>(b, a, N);

    edge_w_kernel<<<(E + 255) / 256, 256>>>(ei, et, N, E);
    edge_scatter_kernel<<<(E + 7) / 8, 256>>>(ei, et, out, N, E);
}